// round 1
// baseline (speedup 1.0000x reference)
#include <cuda_runtime.h>
#include <math.h>

#define B_  4
#define N_  2048
#define D_  1024
#define H_  16
#define DH_ 64

// Scratch: projected Q/K/V in [B*H][N][dh] layout, attention output X in [B*N][D]
__device__ float g_Q[B_ * H_ * N_ * DH_];
__device__ float g_K[B_ * H_ * N_ * DH_];
__device__ float g_V[B_ * H_ * N_ * DH_];
__device__ float g_X[B_ * N_ * D_];

// ---------------------------------------------------------------------------
// 128x128x16 fp32 SGEMM: out = A(MxK) @ W^T + bias, W stored [Ncols][K].
// OUT_HEADS: scatter output columns into [B*H][N][64] head layout.
// ---------------------------------------------------------------------------
template <bool OUT_HEADS, bool HAS_BIAS>
__device__ __forceinline__ void gemm128_body(
    const float* __restrict__ A, const float* __restrict__ W,
    const float* __restrict__ bias, float* __restrict__ out)
{
    __shared__ float As[16][136];   // k-major: As[kk][row]
    __shared__ float Bs[16][136];   // k-major: Bs[kk][col]

    const int tid = threadIdx.x;
    const int tx = tid & 15;
    const int ty = tid >> 4;
    const int m0 = blockIdx.y * 128;
    const int n0 = blockIdx.x * 128;

    float acc[8][8];
#pragma unroll
    for (int i = 0; i < 8; i++)
#pragma unroll
        for (int j = 0; j < 8; j++) acc[i][j] = 0.f;

    for (int kt = 0; kt < D_; kt += 16) {
        // Load A tile and W tile (both 128 rows x 16 k), scatter k-major.
#pragma unroll
        for (int u = 0; u < 2; u++) {
            int f = tid * 2 + u;      // 0..511 float4 slots
            int r = f >> 2;           // row 0..127
            int kv = f & 3;           // float4 index within 16-k row
            float4 av = *(const float4*)(A + (size_t)(m0 + r) * D_ + kt + kv * 4);
            As[kv * 4 + 0][r] = av.x;
            As[kv * 4 + 1][r] = av.y;
            As[kv * 4 + 2][r] = av.z;
            As[kv * 4 + 3][r] = av.w;
            float4 wv = *(const float4*)(W + (size_t)(n0 + r) * D_ + kt + kv * 4);
            Bs[kv * 4 + 0][r] = wv.x;
            Bs[kv * 4 + 1][r] = wv.y;
            Bs[kv * 4 + 2][r] = wv.z;
            Bs[kv * 4 + 3][r] = wv.w;
        }
        __syncthreads();

#pragma unroll
        for (int kk = 0; kk < 16; kk++) {
            float a[8], b[8];
            *(float4*)&a[0] = *(const float4*)&As[kk][ty * 8];
            *(float4*)&a[4] = *(const float4*)&As[kk][ty * 8 + 4];
            *(float4*)&b[0] = *(const float4*)&Bs[kk][tx * 8];
            *(float4*)&b[4] = *(const float4*)&Bs[kk][tx * 8 + 4];
#pragma unroll
            for (int i = 0; i < 8; i++)
#pragma unroll
                for (int j = 0; j < 8; j++) acc[i][j] = fmaf(a[i], b[j], acc[i][j]);
        }
        __syncthreads();
    }

    // Epilogue
#pragma unroll
    for (int i = 0; i < 8; i++) {
        int m = m0 + ty * 8 + i;
#pragma unroll
        for (int j4 = 0; j4 < 2; j4++) {
            int o = n0 + tx * 8 + j4 * 4;
            float4 v;
            v.x = acc[i][j4 * 4 + 0];
            v.y = acc[i][j4 * 4 + 1];
            v.z = acc[i][j4 * 4 + 2];
            v.w = acc[i][j4 * 4 + 3];
            if (HAS_BIAS) {
                v.x += __ldg(bias + o + 0);
                v.y += __ldg(bias + o + 1);
                v.z += __ldg(bias + o + 2);
                v.w += __ldg(bias + o + 3);
            }
            if (OUT_HEADS) {
                int b = m >> 11;          // /2048
                int n = m & 2047;
                int h = o >> 6;
                int di = o & 63;
                *(float4*)(out + (((size_t)(b * H_ + h)) * N_ + n) * DH_ + di) = v;
            } else {
                *(float4*)(out + (size_t)m * D_ + o) = v;
            }
        }
    }
}

// Fused QKV projection: blockIdx.z selects which (input, W, bias, dst) set.
__global__ __launch_bounds__(256) void proj_qkv_kernel(
    const float* __restrict__ xq, const float* __restrict__ xk, const float* __restrict__ xv,
    const float* __restrict__ Wq, const float* __restrict__ bq,
    const float* __restrict__ Wk, const float* __restrict__ bk,
    const float* __restrict__ Wv, const float* __restrict__ bv)
{
    int z = blockIdx.z;
    const float* A = (z == 0) ? xq : (z == 1) ? xk : xv;
    const float* W = (z == 0) ? Wq : (z == 1) ? Wk : Wv;
    const float* b = (z == 0) ? bq : (z == 1) ? bk : bv;
    float* out = (z == 0) ? g_Q : (z == 1) ? g_K : g_V;
    gemm128_body<true, true>(A, W, b, out);
}

// Output projection: reads g_X, writes final output (no bias).
__global__ __launch_bounds__(256) void proj_out_kernel(
    const float* __restrict__ Wo, float* __restrict__ out)
{
    gemm128_body<false, false>(g_X, Wo, nullptr, out);
}

// ---------------------------------------------------------------------------
// Flash attention, fp32, causal. 64 q-rows x 64 k-cols tiles, dh = 64.
// grid: (N/64, B*H), block: 256 threads (16x16, 4x4 per thread).
// ---------------------------------------------------------------------------
#define FPAD 68
#define FLASH_SMEM (4 * 64 * FPAD * 4 + 3 * 64 * 4)

__global__ __launch_bounds__(256) void flash_kernel()
{
    extern __shared__ float sm[];
    float* Qs = sm;                    // [64 d][FPAD] d-major: Qs[d*FPAD + r]
    float* Ks = Qs + 64 * FPAD;        // d-major: Ks[d*FPAD + c]
    float* Vs = Ks + 64 * FPAD;        // c-major: Vs[c*FPAD + e]
    float* Ps = Vs + 64 * FPAD;        // c-major: Ps[c*FPAD + r]
    float* mrow = Ps + 64 * FPAD;      // [64]
    float* lrow = mrow + 64;           // [64]
    float* srow = lrow + 64;           // [64] per-tile rescale factor

    const int tid = threadIdx.x;
    const int tx = tid & 15;
    const int ty = tid >> 4;
    const int qt = blockIdx.x;         // q tile 0..31
    const int bh = blockIdx.y;         // 0..63
    const int qi0 = qt * 64;

    const float* Qg = g_Q + (size_t)bh * N_ * DH_;
    const float* Kg = g_K + (size_t)bh * N_ * DH_;
    const float* Vg = g_V + (size_t)bh * N_ * DH_;

    // Load Q tile transposed (d-major)
#pragma unroll
    for (int u = 0; u < 4; u++) {
        int f = tid + 256 * u;         // 0..1023 float4 slots
        int r = f >> 4;                // row 0..63
        int dv = f & 15;               // float4 along dh
        float4 v = *(const float4*)(Qg + (size_t)(qi0 + r) * DH_ + dv * 4);
        Qs[(dv * 4 + 0) * FPAD + r] = v.x;
        Qs[(dv * 4 + 1) * FPAD + r] = v.y;
        Qs[(dv * 4 + 2) * FPAD + r] = v.z;
        Qs[(dv * 4 + 3) * FPAD + r] = v.w;
    }
    if (tid < 64) { mrow[tid] = -1e30f; lrow[tid] = 0.f; }

    float o[4][4];
#pragma unroll
    for (int i = 0; i < 4; i++)
#pragma unroll
        for (int j = 0; j < 4; j++) o[i][j] = 0.f;

    for (int kt2 = 0; kt2 <= qt; kt2++) {
        const int kj0 = kt2 * 64;
        __syncthreads();  // previous iteration done with Ks/Vs/Ps (+ Q/m/l init on first)

        // Load K transposed (d-major), V direct (c-major)
#pragma unroll
        for (int u = 0; u < 4; u++) {
            int f = tid + 256 * u;
            int r = f >> 4;
            int dv = f & 15;
            float4 kv = *(const float4*)(Kg + (size_t)(kj0 + r) * DH_ + dv * 4);
            Ks[(dv * 4 + 0) * FPAD + r] = kv.x;
            Ks[(dv * 4 + 1) * FPAD + r] = kv.y;
            Ks[(dv * 4 + 2) * FPAD + r] = kv.z;
            Ks[(dv * 4 + 3) * FPAD + r] = kv.w;
            float4 vv = *(const float4*)(Vg + (size_t)(kj0 + r) * DH_ + dv * 4);
            *(float4*)&Vs[r * FPAD + dv * 4] = vv;
        }
        __syncthreads();

        // S = Q @ K^T  (4x4 per thread)
        float s[4][4];
#pragma unroll
        for (int i = 0; i < 4; i++)
#pragma unroll
            for (int j = 0; j < 4; j++) s[i][j] = 0.f;
#pragma unroll 16
        for (int d = 0; d < 64; d++) {
            float4 a = *(const float4*)&Qs[d * FPAD + ty * 4];
            float4 b = *(const float4*)&Ks[d * FPAD + tx * 4];
            float av[4] = {a.x, a.y, a.z, a.w};
            float bv[4] = {b.x, b.y, b.z, b.w};
#pragma unroll
            for (int i = 0; i < 4; i++)
#pragma unroll
                for (int j = 0; j < 4; j++) s[i][j] = fmaf(av[i], bv[j], s[i][j]);
        }

        // Scale + causal mask, write S transposed to Ps[c][r]
        const bool diag = (kt2 == qt);
#pragma unroll
        for (int i = 0; i < 4; i++) {
            int qi = qi0 + ty * 4 + i;
#pragma unroll
            for (int j = 0; j < 4; j++) {
                int kj = kj0 + tx * 4 + j;
                float v = s[i][j] * 0.125f;   // dh^-0.5 = 1/8
                if (diag && kj > qi) v = -1e30f;
                Ps[(tx * 4 + j) * FPAD + (ty * 4 + i)] = v;
            }
        }
        __syncthreads();

        // Per-row online softmax update (64 row threads; stride-FPAD column
        // reads are conflict-free across a warp)
        if (tid < 64) {
            int r = tid;
            float mold = mrow[r];
            float rmax = -1e30f;
#pragma unroll 8
            for (int c = 0; c < 64; c++) rmax = fmaxf(rmax, Ps[c * FPAD + r]);
            float mnew = fmaxf(mold, rmax);
            float sc = __expf(mold - mnew);
            float sum = 0.f;
#pragma unroll 8
            for (int c = 0; c < 64; c++) {
                float p = __expf(Ps[c * FPAD + r] - mnew);
                Ps[c * FPAD + r] = p;
                sum += p;
            }
            mrow[r] = mnew;
            lrow[r] = lrow[r] * sc + sum;
            srow[r] = sc;
        }
        __syncthreads();

        // O = O*scale + P @ V
        float scl[4];
#pragma unroll
        for (int i = 0; i < 4; i++) scl[i] = srow[ty * 4 + i];
#pragma unroll
        for (int i = 0; i < 4; i++)
#pragma unroll
            for (int j = 0; j < 4; j++) o[i][j] *= scl[i];
#pragma unroll 16
        for (int c = 0; c < 64; c++) {
            float4 a = *(const float4*)&Ps[c * FPAD + ty * 4];
            float4 b = *(const float4*)&Vs[c * FPAD + tx * 4];
            float av[4] = {a.x, a.y, a.z, a.w};
            float bv[4] = {b.x, b.y, b.z, b.w};
#pragma unroll
            for (int i = 0; i < 4; i++)
#pragma unroll
                for (int j = 0; j < 4; j++) o[i][j] = fmaf(av[i], bv[j], o[i][j]);
        }
    }

    // Epilogue: divide by l, write to g_X[b][n][h*64 + e]
    const int b = bh >> 4;
    const int h = bh & 15;
#pragma unroll
    for (int i = 0; i < 4; i++) {
        int r = ty * 4 + i;
        float inv = 1.f / lrow[r];
        float4 v;
        v.x = o[i][0] * inv;
        v.y = o[i][1] * inv;
        v.z = o[i][2] * inv;
        v.w = o[i][3] * inv;
        *(float4*)(g_X + ((size_t)b * N_ + qi0 + r) * D_ + h * DH_ + tx * 4) = v;
    }
}

// ---------------------------------------------------------------------------
extern "C" void kernel_launch(void* const* d_in, const int* in_sizes, int n_in,
                              void* d_out, int out_size)
{
    const float* q  = (const float*)d_in[0];
    const float* k  = (const float*)d_in[1];
    const float* v  = (const float*)d_in[2];
    const float* Wq = (const float*)d_in[3];
    const float* bq = (const float*)d_in[4];
    const float* Wk = (const float*)d_in[5];
    const float* bk = (const float*)d_in[6];
    const float* Wv = (const float*)d_in[7];
    const float* bv = (const float*)d_in[8];
    const float* Wo = (const float*)d_in[9];
    float* out = (float*)d_out;

    // QKV projections: M=8192 (y=64 tiles), N=1024 (x=8 tiles), z selects q/k/v
    dim3 gp(8, 64, 3);
    proj_qkv_kernel<<<gp, 256>>>(q, k, v, Wq, bq, Wk, bk, Wv, bv);

    // Flash attention: 32 q-tiles x 64 (b,h) pairs
    cudaFuncSetAttribute(flash_kernel, cudaFuncAttributeMaxDynamicSharedMemorySize,
                         FLASH_SMEM);
    dim3 gf(N_ / 64, B_ * H_);
    flash_kernel<<<gf, 256, FLASH_SMEM>>>();

    // Output projection
    dim3 go(8, 64, 1);
    proj_out_kernel<<<go, 256>>>(Wo, out);
}

// round 3
// speedup vs baseline: 1.6454x; 1.6454x over previous
#include <cuda_runtime.h>
#include <cstdint>
#include <math.h>

#define B_  4
#define N_  2048
#define D_  1024
#define H_  16
#define DH_ 64

// Scratch: projected Q/K/V in [B*H][N][dh] layout, attention output X in [B*N][D]
__device__ float g_Q[B_ * H_ * N_ * DH_];
__device__ float g_K[B_ * H_ * N_ * DH_];
__device__ float g_V[B_ * H_ * N_ * DH_];
__device__ float g_X[B_ * N_ * D_];

__device__ __forceinline__ uint32_t f2tf32(float x) {
    uint32_t r;
    asm("cvt.rna.tf32.f32 %0, %1;" : "=r"(r) : "f"(x));
    return r;
}

__device__ __forceinline__ void mma_tf32_16x8x8(
    float& c0, float& c1, float& c2, float& c3,
    uint32_t a0, uint32_t a1, uint32_t a2, uint32_t a3,
    uint32_t b0, uint32_t b1)
{
    asm volatile(
        "mma.sync.aligned.m16n8k8.row.col.f32.tf32.tf32.f32 "
        "{%0,%1,%2,%3}, {%4,%5,%6,%7}, {%8,%9}, {%0,%1,%2,%3};"
        : "+f"(c0), "+f"(c1), "+f"(c2), "+f"(c3)
        : "r"(a0), "r"(a1), "r"(a2), "r"(a3), "r"(b0), "r"(b1));
}

// ===========================================================================
// tf32 mma.sync GEMM: C[M,1024] = A[M,1024] @ W^T (+bias), W row-major [N][K].
// CTA tile 128x128, k-tile 32. 8 warps (4 m x 2 n), warp tile 32x64.
// Smem: row-major tiles with padded k-stride 36 (conflict-free frag loads).
// ===========================================================================
#define KSTR 36   // padded k stride in floats

template <bool OUT_HEADS, bool HAS_BIAS>
__device__ __forceinline__ void gemm_mma_body(
    const float* __restrict__ A, const float* __restrict__ W,
    const float* __restrict__ bias, float* __restrict__ out)
{
    __shared__ uint32_t As[128 * KSTR];
    __shared__ uint32_t Bs[128 * KSTR];

    const int tid  = threadIdx.x;
    const int wid  = tid >> 5;
    const int lane = tid & 31;
    const int g    = lane >> 2;     // group id 0..7
    const int tig  = lane & 3;      // thread in group 0..3
    const int wm   = wid & 3;       // warp m 0..3  (32 rows each)
    const int wn   = wid >> 2;      // warp n 0..1  (64 cols each)
    const int m0   = blockIdx.y * 128;
    const int n0   = blockIdx.x * 128;

    float c[2][8][4];
#pragma unroll
    for (int t = 0; t < 2; t++)
#pragma unroll
        for (int j = 0; j < 8; j++)
#pragma unroll
            for (int e = 0; e < 4; e++) c[t][j][e] = 0.f;

    for (int kt = 0; kt < D_; kt += 32) {
        // Load 128x32 tiles of A and W, convert to tf32, store padded row-major.
#pragma unroll
        for (int u = 0; u < 4; u++) {
            int f   = tid + 256 * u;          // 0..1023 float4 slots
            int row = f >> 3;                 // 0..127
            int q   = f & 7;                  // float4 within 32-k row
            float4 av = __ldg((const float4*)(A + (size_t)(m0 + row) * D_ + kt + q * 4));
            uint4 at;
            at.x = f2tf32(av.x); at.y = f2tf32(av.y);
            at.z = f2tf32(av.z); at.w = f2tf32(av.w);
            *(uint4*)&As[row * KSTR + q * 4] = at;
            float4 wv = __ldg((const float4*)(W + (size_t)(n0 + row) * D_ + kt + q * 4));
            uint4 wt;
            wt.x = f2tf32(wv.x); wt.y = f2tf32(wv.y);
            wt.z = f2tf32(wv.z); wt.w = f2tf32(wv.w);
            *(uint4*)&Bs[row * KSTR + q * 4] = wt;
        }
        __syncthreads();

#pragma unroll
        for (int kk = 0; kk < 32; kk += 8) {
            // A fragments: 2 m-tiles
            uint32_t a[2][4];
#pragma unroll
            for (int t = 0; t < 2; t++) {
                int r = (wm * 32 + t * 16 + g) * KSTR + kk + tig;
                a[t][0] = As[r];
                a[t][1] = As[r + 8 * KSTR];
                a[t][2] = As[r + 4];
                a[t][3] = As[r + 8 * KSTR + 4];
            }
            // B fragments: 8 n-tiles
            uint32_t b[8][2];
#pragma unroll
            for (int j = 0; j < 8; j++) {
                int r = (wn * 64 + j * 8 + g) * KSTR + kk + tig;
                b[j][0] = Bs[r];
                b[j][1] = Bs[r + 4];
            }
#pragma unroll
            for (int t = 0; t < 2; t++)
#pragma unroll
                for (int j = 0; j < 8; j++)
                    mma_tf32_16x8x8(c[t][j][0], c[t][j][1], c[t][j][2], c[t][j][3],
                                    a[t][0], a[t][1], a[t][2], a[t][3],
                                    b[j][0], b[j][1]);
        }
        __syncthreads();
    }

    // Epilogue: c0/c1 -> row r0, c2/c3 -> row r0+8, cols col..col+1
#pragma unroll
    for (int t = 0; t < 2; t++) {
        const int r0 = m0 + wm * 32 + t * 16 + g;
#pragma unroll
        for (int j = 0; j < 8; j++) {
            const int col = n0 + wn * 64 + j * 8 + tig * 2;
            float2 v0 = make_float2(c[t][j][0], c[t][j][1]);
            float2 v1 = make_float2(c[t][j][2], c[t][j][3]);
            if (HAS_BIAS) {
                float2 bv = *(const float2*)(bias + col);
                v0.x += bv.x; v0.y += bv.y;
                v1.x += bv.x; v1.y += bv.y;
            }
            if (OUT_HEADS) {
                const int h = col >> 6;
                const int di = col & 63;
                const int b0i = r0 >> 11, n0i = r0 & 2047;
                const int r1 = r0 + 8;
                const int b1i = r1 >> 11, n1i = r1 & 2047;
                *(float2*)(out + (((size_t)(b0i * H_ + h)) * N_ + n0i) * DH_ + di) = v0;
                *(float2*)(out + (((size_t)(b1i * H_ + h)) * N_ + n1i) * DH_ + di) = v1;
            } else {
                *(float2*)(out + (size_t)r0 * D_ + col) = v0;
                *(float2*)(out + (size_t)(r0 + 8) * D_ + col) = v1;
            }
        }
    }
}

__global__ __launch_bounds__(256, 2)
void proj_qkv_mma(const float* __restrict__ xq, const float* __restrict__ xk,
                  const float* __restrict__ xv,
                  const float* __restrict__ Wq, const float* __restrict__ bq,
                  const float* __restrict__ Wk, const float* __restrict__ bk,
                  const float* __restrict__ Wv, const float* __restrict__ bv)
{
    int z = blockIdx.z;
    const float* A = (z == 0) ? xq : (z == 1) ? xk : xv;
    const float* W = (z == 0) ? Wq : (z == 1) ? Wk : Wv;
    const float* b = (z == 0) ? bq : (z == 1) ? bk : bv;
    float* out = (z == 0) ? g_Q : (z == 1) ? g_K : g_V;
    gemm_mma_body<true, true>(A, W, b, out);
}

__global__ __launch_bounds__(256, 2)
void proj_out_mma(const float* __restrict__ Wo, float* __restrict__ out)
{
    gemm_mma_body<false, false>(g_X, Wo, nullptr, out);
}

// ---------------------------------------------------------------------------
// Flash attention, fp32, causal. 64 q-rows x 64 k-cols tiles, dh = 64.
// grid: (N/64, B*H), block: 256 threads (16x16, 4x4 per thread).
// ---------------------------------------------------------------------------
#define FPAD 68
#define FLASH_SMEM (4 * 64 * FPAD * 4 + 3 * 64 * 4)

__global__ __launch_bounds__(256) void flash_kernel()
{
    extern __shared__ float smf[];
    float* Qs = smf;                   // d-major: Qs[d*FPAD + r]
    float* Ks = Qs + 64 * FPAD;        // d-major: Ks[d*FPAD + c]
    float* Vs = Ks + 64 * FPAD;        // c-major: Vs[c*FPAD + e]
    float* Ps = Vs + 64 * FPAD;        // c-major: Ps[c*FPAD + r]
    float* mrow = Ps + 64 * FPAD;
    float* lrow = mrow + 64;
    float* srow = lrow + 64;

    const int tid = threadIdx.x;
    const int tx = tid & 15;
    const int ty = tid >> 4;
    const int qt = blockIdx.x;
    const int bh = blockIdx.y;
    const int qi0 = qt * 64;

    const float* Qg = g_Q + (size_t)bh * N_ * DH_;
    const float* Kg = g_K + (size_t)bh * N_ * DH_;
    const float* Vg = g_V + (size_t)bh * N_ * DH_;

#pragma unroll
    for (int u = 0; u < 4; u++) {
        int f = tid + 256 * u;
        int r = f >> 4;
        int dv = f & 15;
        float4 v = *(const float4*)(Qg + (size_t)(qi0 + r) * DH_ + dv * 4);
        Qs[(dv * 4 + 0) * FPAD + r] = v.x;
        Qs[(dv * 4 + 1) * FPAD + r] = v.y;
        Qs[(dv * 4 + 2) * FPAD + r] = v.z;
        Qs[(dv * 4 + 3) * FPAD + r] = v.w;
    }
    if (tid < 64) { mrow[tid] = -1e30f; lrow[tid] = 0.f; }

    float o[4][4];
#pragma unroll
    for (int i = 0; i < 4; i++)
#pragma unroll
        for (int j = 0; j < 4; j++) o[i][j] = 0.f;

    for (int kt2 = 0; kt2 <= qt; kt2++) {
        const int kj0 = kt2 * 64;
        __syncthreads();

#pragma unroll
        for (int u = 0; u < 4; u++) {
            int f = tid + 256 * u;
            int r = f >> 4;
            int dv = f & 15;
            float4 kv = *(const float4*)(Kg + (size_t)(kj0 + r) * DH_ + dv * 4);
            Ks[(dv * 4 + 0) * FPAD + r] = kv.x;
            Ks[(dv * 4 + 1) * FPAD + r] = kv.y;
            Ks[(dv * 4 + 2) * FPAD + r] = kv.z;
            Ks[(dv * 4 + 3) * FPAD + r] = kv.w;
            float4 vv = *(const float4*)(Vg + (size_t)(kj0 + r) * DH_ + dv * 4);
            *(float4*)&Vs[r * FPAD + dv * 4] = vv;
        }
        __syncthreads();

        float s[4][4];
#pragma unroll
        for (int i = 0; i < 4; i++)
#pragma unroll
            for (int j = 0; j < 4; j++) s[i][j] = 0.f;
#pragma unroll 16
        for (int d = 0; d < 64; d++) {
            float4 a = *(const float4*)&Qs[d * FPAD + ty * 4];
            float4 b = *(const float4*)&Ks[d * FPAD + tx * 4];
            float av[4] = {a.x, a.y, a.z, a.w};
            float bv[4] = {b.x, b.y, b.z, b.w};
#pragma unroll
            for (int i = 0; i < 4; i++)
#pragma unroll
                for (int j = 0; j < 4; j++) s[i][j] = fmaf(av[i], bv[j], s[i][j]);
        }

        const bool diag = (kt2 == qt);
#pragma unroll
        for (int i = 0; i < 4; i++) {
            int qi = qi0 + ty * 4 + i;
#pragma unroll
            for (int j = 0; j < 4; j++) {
                int kj = kj0 + tx * 4 + j;
                float v = s[i][j] * 0.125f;
                if (diag && kj > qi) v = -1e30f;
                Ps[(tx * 4 + j) * FPAD + (ty * 4 + i)] = v;
            }
        }
        __syncthreads();

        if (tid < 64) {
            int r = tid;
            float mold = mrow[r];
            float rmax = -1e30f;
#pragma unroll 8
            for (int c = 0; c < 64; c++) rmax = fmaxf(rmax, Ps[c * FPAD + r]);
            float mnew = fmaxf(mold, rmax);
            float sc = __expf(mold - mnew);
            float sum = 0.f;
#pragma unroll 8
            for (int c = 0; c < 64; c++) {
                float p = __expf(Ps[c * FPAD + r] - mnew);
                Ps[c * FPAD + r] = p;
                sum += p;
            }
            mrow[r] = mnew;
            lrow[r] = lrow[r] * sc + sum;
            srow[r] = sc;
        }
        __syncthreads();

        float scl[4];
#pragma unroll
        for (int i = 0; i < 4; i++) scl[i] = srow[ty * 4 + i];
#pragma unroll
        for (int i = 0; i < 4; i++)
#pragma unroll
            for (int j = 0; j < 4; j++) o[i][j] *= scl[i];
#pragma unroll 16
        for (int c = 0; c < 64; c++) {
            float4 a = *(const float4*)&Ps[c * FPAD + ty * 4];
            float4 b = *(const float4*)&Vs[c * FPAD + tx * 4];
            float av[4] = {a.x, a.y, a.z, a.w};
            float bv[4] = {b.x, b.y, b.z, b.w};
#pragma unroll
            for (int i = 0; i < 4; i++)
#pragma unroll
                for (int j = 0; j < 4; j++) o[i][j] = fmaf(av[i], bv[j], o[i][j]);
        }
    }

    const int b = bh >> 4;
    const int h = bh & 15;
#pragma unroll
    for (int i = 0; i < 4; i++) {
        int r = ty * 4 + i;
        float inv = 1.f / lrow[r];
        float4 v;
        v.x = o[i][0] * inv;
        v.y = o[i][1] * inv;
        v.z = o[i][2] * inv;
        v.w = o[i][3] * inv;
        *(float4*)(g_X + ((size_t)b * N_ + qi0 + r) * D_ + h * DH_ + tx * 4) = v;
    }
}

// ---------------------------------------------------------------------------
extern "C" void kernel_launch(void* const* d_in, const int* in_sizes, int n_in,
                              void* d_out, int out_size)
{
    const float* q  = (const float*)d_in[0];
    const float* k  = (const float*)d_in[1];
    const float* v  = (const float*)d_in[2];
    const float* Wq = (const float*)d_in[3];
    const float* bq = (const float*)d_in[4];
    const float* Wk = (const float*)d_in[5];
    const float* bk = (const float*)d_in[6];
    const float* Wv = (const float*)d_in[7];
    const float* bv = (const float*)d_in[8];
    const float* Wo = (const float*)d_in[9];
    float* out = (float*)d_out;

    cudaFuncSetAttribute(flash_kernel, cudaFuncAttributeMaxDynamicSharedMemorySize,
                         FLASH_SMEM);

    // QKV projections: M=8192 -> 64 row-tiles, N=1024 -> 8 col-tiles, z = q/k/v
    dim3 gp(8, 64, 3);
    proj_qkv_mma<<<gp, 256>>>(q, k, v, Wq, bq, Wk, bk, Wv, bv);

    // Flash attention: 32 q-tiles x 64 (b,h) pairs
    dim3 gf(N_ / 64, B_ * H_);
    flash_kernel<<<gf, 256, FLASH_SMEM>>>();

    // Output projection
    dim3 go(8, 64, 1);
    proj_out_mma<<<go, 256>>>(Wo, out);
}

// round 4
// speedup vs baseline: 3.2881x; 1.9984x over previous
#include <cuda_runtime.h>
#include <cstdint>
#include <math.h>

#define B_  4
#define N_  2048
#define D_  1024
#define H_  16
#define DH_ 64

// Scratch: projected Q/K/V in [B*H][N][dh] layout, attention output X in [B*N][D]
__device__ float g_Q[B_ * H_ * N_ * DH_];
__device__ float g_K[B_ * H_ * N_ * DH_];
__device__ float g_V[B_ * H_ * N_ * DH_];
__device__ float g_X[B_ * N_ * D_];

__device__ __forceinline__ uint32_t f2tf32(float x) {
    uint32_t r;
    asm("cvt.rna.tf32.f32 %0, %1;" : "=r"(r) : "f"(x));
    return r;
}
__device__ __forceinline__ float ex2f(float x) {
    float y;
    asm("ex2.approx.ftz.f32 %0, %1;" : "=f"(y) : "f"(x));
    return y;
}

__device__ __forceinline__ void mma_tf32_16x8x8(
    float& c0, float& c1, float& c2, float& c3,
    uint32_t a0, uint32_t a1, uint32_t a2, uint32_t a3,
    uint32_t b0, uint32_t b1)
{
    asm volatile(
        "mma.sync.aligned.m16n8k8.row.col.f32.tf32.tf32.f32 "
        "{%0,%1,%2,%3}, {%4,%5,%6,%7}, {%8,%9}, {%0,%1,%2,%3};"
        : "+f"(c0), "+f"(c1), "+f"(c2), "+f"(c3)
        : "r"(a0), "r"(a1), "r"(a2), "r"(a3), "r"(b0), "r"(b1));
}

// ===========================================================================
// tf32 mma.sync GEMM: C[M,1024] = A[M,1024] @ W^T (+bias), W row-major [N][K].
// CTA tile 128x128, k-tile 32. 8 warps (4 m x 2 n), warp tile 32x64.
// ===========================================================================
#define KSTR 36   // padded k stride in floats

template <bool OUT_HEADS, bool HAS_BIAS>
__device__ __forceinline__ void gemm_mma_body(
    const float* __restrict__ A, const float* __restrict__ W,
    const float* __restrict__ bias, float* __restrict__ out)
{
    __shared__ uint32_t As[128 * KSTR];
    __shared__ uint32_t Bs[128 * KSTR];

    const int tid  = threadIdx.x;
    const int wid  = tid >> 5;
    const int lane = tid & 31;
    const int g    = lane >> 2;
    const int tig  = lane & 3;
    const int wm   = wid & 3;
    const int wn   = wid >> 2;
    const int m0   = blockIdx.y * 128;
    const int n0   = blockIdx.x * 128;

    float c[2][8][4];
#pragma unroll
    for (int t = 0; t < 2; t++)
#pragma unroll
        for (int j = 0; j < 8; j++)
#pragma unroll
            for (int e = 0; e < 4; e++) c[t][j][e] = 0.f;

    for (int kt = 0; kt < D_; kt += 32) {
#pragma unroll
        for (int u = 0; u < 4; u++) {
            int f   = tid + 256 * u;
            int row = f >> 3;
            int q   = f & 7;
            float4 av = __ldg((const float4*)(A + (size_t)(m0 + row) * D_ + kt + q * 4));
            uint4 at;
            at.x = f2tf32(av.x); at.y = f2tf32(av.y);
            at.z = f2tf32(av.z); at.w = f2tf32(av.w);
            *(uint4*)&As[row * KSTR + q * 4] = at;
            float4 wv = __ldg((const float4*)(W + (size_t)(n0 + row) * D_ + kt + q * 4));
            uint4 wt;
            wt.x = f2tf32(wv.x); wt.y = f2tf32(wv.y);
            wt.z = f2tf32(wv.z); wt.w = f2tf32(wv.w);
            *(uint4*)&Bs[row * KSTR + q * 4] = wt;
        }
        __syncthreads();

#pragma unroll
        for (int kk = 0; kk < 32; kk += 8) {
            uint32_t a[2][4];
#pragma unroll
            for (int t = 0; t < 2; t++) {
                int r = (wm * 32 + t * 16 + g) * KSTR + kk + tig;
                a[t][0] = As[r];
                a[t][1] = As[r + 8 * KSTR];
                a[t][2] = As[r + 4];
                a[t][3] = As[r + 8 * KSTR + 4];
            }
            uint32_t b[8][2];
#pragma unroll
            for (int j = 0; j < 8; j++) {
                int r = (wn * 64 + j * 8 + g) * KSTR + kk + tig;
                b[j][0] = Bs[r];
                b[j][1] = Bs[r + 4];
            }
#pragma unroll
            for (int t = 0; t < 2; t++)
#pragma unroll
                for (int j = 0; j < 8; j++)
                    mma_tf32_16x8x8(c[t][j][0], c[t][j][1], c[t][j][2], c[t][j][3],
                                    a[t][0], a[t][1], a[t][2], a[t][3],
                                    b[j][0], b[j][1]);
        }
        __syncthreads();
    }

#pragma unroll
    for (int t = 0; t < 2; t++) {
        const int r0 = m0 + wm * 32 + t * 16 + g;
#pragma unroll
        for (int j = 0; j < 8; j++) {
            const int col = n0 + wn * 64 + j * 8 + tig * 2;
            float2 v0 = make_float2(c[t][j][0], c[t][j][1]);
            float2 v1 = make_float2(c[t][j][2], c[t][j][3]);
            if (HAS_BIAS) {
                float2 bv = *(const float2*)(bias + col);
                v0.x += bv.x; v0.y += bv.y;
                v1.x += bv.x; v1.y += bv.y;
            }
            if (OUT_HEADS) {
                const int h = col >> 6;
                const int di = col & 63;
                const int b0i = r0 >> 11, n0i = r0 & 2047;
                const int r1 = r0 + 8;
                const int b1i = r1 >> 11, n1i = r1 & 2047;
                *(float2*)(out + (((size_t)(b0i * H_ + h)) * N_ + n0i) * DH_ + di) = v0;
                *(float2*)(out + (((size_t)(b1i * H_ + h)) * N_ + n1i) * DH_ + di) = v1;
            } else {
                *(float2*)(out + (size_t)r0 * D_ + col) = v0;
                *(float2*)(out + (size_t)(r0 + 8) * D_ + col) = v1;
            }
        }
    }
}

__global__ __launch_bounds__(256, 2)
void proj_qkv_mma(const float* __restrict__ xq, const float* __restrict__ xk,
                  const float* __restrict__ xv,
                  const float* __restrict__ Wq, const float* __restrict__ bq,
                  const float* __restrict__ Wk, const float* __restrict__ bk,
                  const float* __restrict__ Wv, const float* __restrict__ bv)
{
    int z = blockIdx.z;
    const float* A = (z == 0) ? xq : (z == 1) ? xk : xv;
    const float* W = (z == 0) ? Wq : (z == 1) ? Wk : Wv;
    const float* b = (z == 0) ? bq : (z == 1) ? bk : bv;
    float* out = (z == 0) ? g_Q : (z == 1) ? g_K : g_V;
    gemm_mma_body<true, true>(A, W, b, out);
}

__global__ __launch_bounds__(256, 2)
void proj_out_mma(const float* __restrict__ Wo, float* __restrict__ out)
{
    gemm_mma_body<false, false>(g_X, Wo, nullptr, out);
}

// ===========================================================================
// Tensor-core flash attention (tf32 mma.sync), causal, dh=64.
// CTA: 128 threads (4 warps). 64-query tile; warp w owns rows w*16..w*16+15.
// Q pre-scaled by dh^-0.5 * log2(e); softmax in exp2 domain via MUFU ex2.
// grid: (N/64, B*H).
// ===========================================================================
#define QSTR 68
#define VSTR 72
#define FL_SMEM ((64 * QSTR * 2 + 64 * VSTR) * 4)

__global__ __launch_bounds__(128, 4) void flash_mma_kernel()
{
    extern __shared__ uint32_t fsm[];
    uint32_t* Qs = fsm;                 // [64][QSTR] row-major (q rows x dh)
    uint32_t* Ks = Qs + 64 * QSTR;      // [64][QSTR] (k rows x dh)
    uint32_t* Vs = Ks + 64 * QSTR;      // [64][VSTR] (k rows x dh)

    const int tid  = threadIdx.x;
    const int wq   = tid >> 5;
    const int lane = tid & 31;
    const int g    = lane >> 2;
    const int tig  = lane & 3;
    const int qt   = blockIdx.x;
    const int bh   = blockIdx.y;
    const int qi0  = qt * 64;

    const float* Qg = g_Q + (size_t)bh * N_ * DH_;
    const float* Kg = g_K + (size_t)bh * N_ * DH_;
    const float* Vg = g_V + (size_t)bh * N_ * DH_;

    const float qscale = 0.125f * 1.44269504088896340736f; // dh^-0.5 * log2(e)

    // Stage Q tile (tf32, pre-scaled)
#pragma unroll
    for (int u = 0; u < 4; u++) {
        int f  = tid + 128 * u;          // 0..511 float4 slots
        int r  = f >> 3;                 // row 0..63
        int dv = f & 7;                  // float4 within 64-wide row... (64/4=16) -> need 16
        (void)r; (void)dv;
    }
    // 64 rows x 16 float4 = 1024 slots over 128 threads = 8 iters
#pragma unroll
    for (int u = 0; u < 8; u++) {
        int f  = tid + 128 * u;
        int r  = f >> 4;
        int dv = f & 15;
        float4 v = *(const float4*)(Qg + (size_t)(qi0 + r) * DH_ + dv * 4);
        uint4 t;
        t.x = f2tf32(v.x * qscale); t.y = f2tf32(v.y * qscale);
        t.z = f2tf32(v.z * qscale); t.w = f2tf32(v.w * qscale);
        *(uint4*)&Qs[r * QSTR + dv * 4] = t;
    }

    float m0r = -1e30f, m1r = -1e30f;
    float l0r = 0.f, l1r = 0.f;
    float O[8][4];
#pragma unroll
    for (int j = 0; j < 8; j++)
#pragma unroll
        for (int e = 0; e < 4; e++) O[j][e] = 0.f;

    const int row0 = qi0 + wq * 16 + g;
    const int row1 = row0 + 8;

    for (int kt2 = 0; kt2 <= qt; kt2++) {
        const int kj0 = kt2 * 64;
        __syncthreads();   // previous iteration done with Ks/Vs (and Q staged on first)

        // Stage K (tf32) and V (tf32)
#pragma unroll
        for (int u = 0; u < 8; u++) {
            int f  = tid + 128 * u;
            int r  = f >> 4;
            int dv = f & 15;
            float4 kv = *(const float4*)(Kg + (size_t)(kj0 + r) * DH_ + dv * 4);
            uint4 kt_;
            kt_.x = f2tf32(kv.x); kt_.y = f2tf32(kv.y);
            kt_.z = f2tf32(kv.z); kt_.w = f2tf32(kv.w);
            *(uint4*)&Ks[r * QSTR + dv * 4] = kt_;
            float4 vv = *(const float4*)(Vg + (size_t)(kj0 + r) * DH_ + dv * 4);
            uint4 vt;
            vt.x = f2tf32(vv.x); vt.y = f2tf32(vv.y);
            vt.z = f2tf32(vv.z); vt.w = f2tf32(vv.w);
            *(uint4*)&Vs[r * VSTR + dv * 4] = vt;
        }
        __syncthreads();

        // ---- S = Qs @ Ks^T  (m16 x n64, k=64) ----
        float S[8][4];
#pragma unroll
        for (int j = 0; j < 8; j++)
#pragma unroll
            for (int e = 0; e < 4; e++) S[j][e] = 0.f;

#pragma unroll
        for (int kb = 0; kb < 8; kb++) {
            const int ar = (wq * 16 + g) * QSTR + kb * 8 + tig;
            uint32_t a0 = Qs[ar];
            uint32_t a1 = Qs[ar + 8 * QSTR];
            uint32_t a2 = Qs[ar + 4];
            uint32_t a3 = Qs[ar + 8 * QSTR + 4];
#pragma unroll
            for (int j = 0; j < 8; j++) {
                const int br = (j * 8 + g) * QSTR + kb * 8 + tig;
                uint32_t b0 = Ks[br];
                uint32_t b1 = Ks[br + 4];
                mma_tf32_16x8x8(S[j][0], S[j][1], S[j][2], S[j][3],
                                a0, a1, a2, a3, b0, b1);
            }
        }

        // ---- causal mask (diag tile only) ----
        if (kt2 == qt) {
#pragma unroll
            for (int j = 0; j < 8; j++) {
                int c = kj0 + j * 8 + tig * 2;
                if (c     > row0) S[j][0] = -1e30f;
                if (c + 1 > row0) S[j][1] = -1e30f;
                if (c     > row1) S[j][2] = -1e30f;
                if (c + 1 > row1) S[j][3] = -1e30f;
            }
        }

        // ---- online softmax (exp2 domain) ----
        float rmax0 = -1e30f, rmax1 = -1e30f;
#pragma unroll
        for (int j = 0; j < 8; j++) {
            rmax0 = fmaxf(rmax0, fmaxf(S[j][0], S[j][1]));
            rmax1 = fmaxf(rmax1, fmaxf(S[j][2], S[j][3]));
        }
        rmax0 = fmaxf(rmax0, __shfl_xor_sync(0xffffffffu, rmax0, 1));
        rmax0 = fmaxf(rmax0, __shfl_xor_sync(0xffffffffu, rmax0, 2));
        rmax1 = fmaxf(rmax1, __shfl_xor_sync(0xffffffffu, rmax1, 1));
        rmax1 = fmaxf(rmax1, __shfl_xor_sync(0xffffffffu, rmax1, 2));

        float mn0 = fmaxf(m0r, rmax0);
        float mn1 = fmaxf(m1r, rmax1);
        float al0 = ex2f(m0r - mn0);
        float al1 = ex2f(m1r - mn1);
        m0r = mn0; m1r = mn1;

        float sum0 = 0.f, sum1 = 0.f;
        uint32_t P[8][4];
#pragma unroll
        for (int j = 0; j < 8; j++) {
            float p0 = ex2f(S[j][0] - mn0);
            float p1 = ex2f(S[j][1] - mn0);
            float p2 = ex2f(S[j][2] - mn1);
            float p3 = ex2f(S[j][3] - mn1);
            sum0 += p0 + p1;
            sum1 += p2 + p3;
            P[j][0] = f2tf32(p0); P[j][1] = f2tf32(p1);
            P[j][2] = f2tf32(p2); P[j][3] = f2tf32(p3);
        }
        sum0 += __shfl_xor_sync(0xffffffffu, sum0, 1);
        sum0 += __shfl_xor_sync(0xffffffffu, sum0, 2);
        sum1 += __shfl_xor_sync(0xffffffffu, sum1, 1);
        sum1 += __shfl_xor_sync(0xffffffffu, sum1, 2);
        l0r = l0r * al0 + sum0;
        l1r = l1r * al1 + sum1;

#pragma unroll
        for (int j = 0; j < 8; j++) {
            O[j][0] *= al0; O[j][1] *= al0;
            O[j][2] *= al1; O[j][3] *= al1;
        }

        // ---- O += P @ V  (P m16 x k64 via quad shuffles, V from smem) ----
        const int srcA = (lane & ~3) | (tig >> 1);
        const int srcB = srcA + 2;
        const bool oddc = (tig & 1);
#pragma unroll
        for (int kb = 0; kb < 8; kb++) {
            uint32_t v0 = __shfl_sync(0xffffffffu, P[kb][0], srcA);
            uint32_t v1 = __shfl_sync(0xffffffffu, P[kb][1], srcA);
            uint32_t a0 = oddc ? v1 : v0;
            uint32_t w0 = __shfl_sync(0xffffffffu, P[kb][0], srcB);
            uint32_t w1 = __shfl_sync(0xffffffffu, P[kb][1], srcB);
            uint32_t a2 = oddc ? w1 : w0;
            uint32_t x0 = __shfl_sync(0xffffffffu, P[kb][2], srcA);
            uint32_t x1 = __shfl_sync(0xffffffffu, P[kb][3], srcA);
            uint32_t a1 = oddc ? x1 : x0;
            uint32_t y0 = __shfl_sync(0xffffffffu, P[kb][2], srcB);
            uint32_t y1 = __shfl_sync(0xffffffffu, P[kb][3], srcB);
            uint32_t a3 = oddc ? y1 : y0;
#pragma unroll
            for (int j = 0; j < 8; j++) {
                uint32_t b0 = Vs[(kb * 8 + tig) * VSTR + j * 8 + g];
                uint32_t b1 = Vs[(kb * 8 + tig + 4) * VSTR + j * 8 + g];
                mma_tf32_16x8x8(O[j][0], O[j][1], O[j][2], O[j][3],
                                a0, a1, a2, a3, b0, b1);
            }
        }
    }

    // Epilogue: O /= l; write to g_X[b][n][h*64 + e]
    const int b = bh >> 4;
    const int h = bh & 15;
    const float il0 = 1.f / l0r;
    const float il1 = 1.f / l1r;
    float* X0 = g_X + ((size_t)b * N_ + row0) * D_ + h * DH_;
    float* X1 = g_X + ((size_t)b * N_ + row1) * D_ + h * DH_;
#pragma unroll
    for (int j = 0; j < 8; j++) {
        int e = j * 8 + tig * 2;
        *(float2*)(X0 + e) = make_float2(O[j][0] * il0, O[j][1] * il0);
        *(float2*)(X1 + e) = make_float2(O[j][2] * il1, O[j][3] * il1);
    }
}

// ---------------------------------------------------------------------------
extern "C" void kernel_launch(void* const* d_in, const int* in_sizes, int n_in,
                              void* d_out, int out_size)
{
    const float* q  = (const float*)d_in[0];
    const float* k  = (const float*)d_in[1];
    const float* v  = (const float*)d_in[2];
    const float* Wq = (const float*)d_in[3];
    const float* bq = (const float*)d_in[4];
    const float* Wk = (const float*)d_in[5];
    const float* bk = (const float*)d_in[6];
    const float* Wv = (const float*)d_in[7];
    const float* bv = (const float*)d_in[8];
    const float* Wo = (const float*)d_in[9];
    float* out = (float*)d_out;

    cudaFuncSetAttribute(flash_mma_kernel, cudaFuncAttributeMaxDynamicSharedMemorySize,
                         FL_SMEM);

    // QKV projections
    dim3 gp(8, 64, 3);
    proj_qkv_mma<<<gp, 256>>>(q, k, v, Wq, bq, Wk, bk, Wv, bv);

    // Tensor-core flash attention: 32 q-tiles x 64 (b,h) pairs
    dim3 gf(N_ / 64, B_ * H_);
    flash_mma_kernel<<<gf, 128, FL_SMEM>>>();

    // Output projection
    dim3 go(8, 64, 1);
    proj_out_mma<<<go, 256>>>(Wo, out);
}